// round 3
// baseline (speedup 1.0000x reference)
#include <cuda_runtime.h>
#include <cstdint>

#define FULL_MASK 0xffffffffu

// Problem constants
// B=4, T=32, N=4096, F=16, G=64, M=128, K=32, C0=64, C1=128
#define NPTS   4096
#define NGRP   64
#define NANCH  128
#define XYZ_OUT_ELEMS (64 * 128 * 3)   // 24576
#define R2CONST 0.0225f

static __device__ __forceinline__ unsigned long long pack2(float lo, float hi) {
    unsigned long long r;
    asm("mov.b64 %0, {%1, %2};" : "=l"(r) : "f"(lo), "f"(hi));
    return r;
}
static __device__ __forceinline__ void fma2(unsigned long long &acc,
                                            unsigned long long a,
                                            unsigned long long b) {
    asm("fma.rn.f32x2 %0, %1, %2, %0;" : "+l"(acc) : "l"(a), "l"(b));
}
static __device__ __forceinline__ float sum2(unsigned long long v) {
    float a, b;
    asm("mov.b64 {%0, %1}, %2;" : "=f"(a), "=f"(b) : "l"(v));
    return a + b;
}

// ---------------------------------------------------------------------------
// Kernel 1: furthest point sampling. One block per group (64 blocks).
// Writes anchor coords directly into d_out[0 .. 24576) = new_xyzs.
// ---------------------------------------------------------------------------
__global__ __launch_bounds__(512) void fps_kernel(const float* __restrict__ xyzs,
                                                  float* __restrict__ out)
{
    __shared__ float sx[NPTS], sy[NPTS], sz[NPTS];
    __shared__ float wv[16];
    __shared__ int   wi[16];
    __shared__ float bc[3];

    const int g = blockIdx.x;
    const int b = g >> 4;
    const int f = g & 15;
    const int tc = 2 * f;                  // center frame (original index)
    const float* fr = xyzs + (size_t)((b * 32 + tc) * NPTS) * 3;

    const int tid  = threadIdx.x;
    const int lane = tid & 31;
    const int warp = tid >> 5;

    float px[8], py[8], pz[8], dist[8];
#pragma unroll
    for (int j = 0; j < 8; j++) {
        int p = tid * 8 + j;
        float x = fr[p * 3 + 0];
        float y = fr[p * 3 + 1];
        float z = fr[p * 3 + 2];
        px[j] = x; py[j] = y; pz[j] = z;
        sx[p] = x; sy[p] = y; sz[p] = z;
        dist[j] = 1e10f;
    }
    float* anc = out + (size_t)g * NANCH * 3;
    __syncthreads();
    if (tid == 0) {
        bc[0] = sx[0]; bc[1] = sy[0]; bc[2] = sz[0];
        anc[0] = sx[0]; anc[1] = sy[0]; anc[2] = sz[0];
    }
    __syncthreads();

    for (int it = 1; it < NANCH; it++) {
        const float cx = bc[0], cy = bc[1], cz = bc[2];
        float bd = -1.0f;
        int   bi = 0;
#pragma unroll
        for (int j = 0; j < 8; j++) {
            float dx = px[j] - cx, dy = py[j] - cy, dz = pz[j] - cz;
            float d = dx * dx + dy * dy + dz * dz;
            d = fminf(dist[j], d);
            dist[j] = d;
            if (d > bd) { bd = d; bi = tid * 8 + j; }   // strict > keeps earliest index
        }
        // warp argmax (blocked mapping: lower lane = lower point index; strict > keeps first)
#pragma unroll
        for (int off = 16; off > 0; off >>= 1) {
            float ov = __shfl_down_sync(FULL_MASK, bd, off);
            int   oi = __shfl_down_sync(FULL_MASK, bi, off);
            if (ov > bd) { bd = ov; bi = oi; }
        }
        if (lane == 0) { wv[warp] = bd; wi[warp] = bi; }
        __syncthreads();
        if (warp == 0) {
            float v  = (lane < 16) ? wv[lane] : -2.0f;
            int   i2 = (lane < 16) ? wi[lane] : 0;
#pragma unroll
            for (int off = 8; off > 0; off >>= 1) {
                float ov = __shfl_down_sync(FULL_MASK, v, off);
                int   oi = __shfl_down_sync(FULL_MASK, i2, off);
                if (ov > v) { v = ov; i2 = oi; }
            }
            if (lane == 0) {
                float nx = sx[i2], ny = sy[i2], nz = sz[i2];
                bc[0] = nx; bc[1] = ny; bc[2] = nz;
                anc[it * 3 + 0] = nx;
                anc[it * 3 + 1] = ny;
                anc[it * 3 + 2] = nz;
            }
        }
        __syncthreads();
    }
}

// ---------------------------------------------------------------------------
// Kernel 2: ball query + MLP(4->64) + MLP(64->128) + max over neighbors,
// summed over dt in {-1,0,1}. One warp per anchor. 256 thr/block, 1024 blocks.
// ---------------------------------------------------------------------------
__global__ __launch_bounds__(256) void p4d_kernel(const float* __restrict__ xyzs,
                                                  const float* __restrict__ Wd,
                                                  const float* __restrict__ Wm,
                                                  float* __restrict__ out)
{
    __shared__ __align__(16) float Wm_s[128 * 64];
    __shared__ __align__(16) float Wd_s[64 * 4];
    __shared__ int sel[8][32];

    const int tid = threadIdx.x;
    for (int i = tid; i < 128 * 64; i += 256) Wm_s[i] = Wm[i];
    if (tid < 256) Wd_s[tid] = Wd[tid];
    __syncthreads();

    const int lane = tid & 31;
    const int w    = tid >> 5;
    const int a    = blockIdx.x * 8 + w;      // global anchor id 0..8191
    const int g    = a >> 7;
    const int m    = a & 127;
    const int b    = g >> 4;
    const int f    = g & 15;
    const int tc   = 2 * f;

    const float* anc = out + (size_t)(g * NANCH + m) * 3;
    const float ax = anc[0], ay = anc[1], az = anc[2];

    const unsigned long long* Wm2 = (const unsigned long long*)Wm_s;
    const float4*             Wd4 = (const float4*)Wd_s;

    float facc0 = 0.f, facc1 = 0.f, facc2 = 0.f, facc3 = 0.f;

    for (int dti = 0; dti < 3; dti++) {
        const int t = (dti == 0) ? ((f == 0) ? 0 : (tc - 1))
                                 : ((dti == 1) ? tc : (tc + 1));
        const float* fr  = xyzs + (size_t)((b * 32 + t) * NPTS) * 3;
        const float  dtf = (float)(dti - 1);

        // ---- ball query: first 32 in-radius indices (ascending), pad with first
        __syncwarp();
        int cnt = 0;
        for (int base = 0; base < NPTS && cnt < 32; base += 32) {
            const int idx = base + lane;
            const float nx = fr[idx * 3 + 0];
            const float ny = fr[idx * 3 + 1];
            const float nz = fr[idx * 3 + 2];
            const float dx = nx - ax, dy = ny - ay, dz = nz - az;
            const float d2 = dx * dx + dy * dy + dz * dz;
            const bool  pr = d2 < R2CONST;
            const unsigned mask = __ballot_sync(FULL_MASK, pr);
            const int rank = cnt + __popc(mask & ((1u << lane) - 1u));
            if (pr && rank < 32) sel[w][rank] = idx;
            cnt += __popc(mask);
        }
        __syncwarp();
        const int pad = (cnt > 0) ? sel[w][0] : 0;
        const int myN = (lane < cnt) ? sel[w][lane] : pad;

        const float nx = fr[myN * 3 + 0];
        const float ny = fr[myN * 3 + 1];
        const float nz = fr[myN * 3 + 2];
        const float dx = nx - ax, dy = ny - ay, dz = nz - az;

        // ---- h1 = relu(Wd @ [dx,dy,dz,dt]) : 64 values, packed as 32 f32x2
        unsigned long long Hp[32];
#pragma unroll
        for (int i2 = 0; i2 < 32; i2++) {
            const float4 w0 = Wd4[2 * i2];
            const float4 w1 = Wd4[2 * i2 + 1];
            float a0 = fmaxf(w0.x * dx + w0.y * dy + w0.z * dz + w0.w * dtf, 0.f);
            float a1 = fmaxf(w1.x * dx + w1.y * dy + w1.z * dz + w1.w * dtf, 0.f);
            Hp[i2] = pack2(a0, a1);
        }

        // ---- h2 = Wm @ h1; max over the warp's 32 neighbors per channel;
        //      relu(max) == max(relu); accumulate into owner lane's registers.
#pragma unroll
        for (int oh = 0; oh < 4; oh++) {
            float fa = 0.f;
#pragma unroll 2
            for (int ol = 0; ol < 32; ol++) {
                const unsigned long long* wr = Wm2 + ((oh * 32 + ol) << 5);
                unsigned long long acc0 = 0ull, acc1 = 0ull, acc2 = 0ull, acc3 = 0ull;
#pragma unroll
                for (int i2 = 0; i2 < 32; i2 += 4) {
                    fma2(acc0, wr[i2 + 0], Hp[i2 + 0]);
                    fma2(acc1, wr[i2 + 1], Hp[i2 + 1]);
                    fma2(acc2, wr[i2 + 2], Hp[i2 + 2]);
                    fma2(acc3, wr[i2 + 3], Hp[i2 + 3]);
                }
                float s = (sum2(acc0) + sum2(acc1)) + (sum2(acc2) + sum2(acc3));
#pragma unroll
                for (int off = 16; off > 0; off >>= 1)
                    s = fmaxf(s, __shfl_xor_sync(FULL_MASK, s, off));
                if (ol == lane) fa += fmaxf(s, 0.f);
            }
            if      (oh == 0) facc0 += fa;
            else if (oh == 1) facc1 += fa;
            else if (oh == 2) facc2 += fa;
            else              facc3 += fa;
        }
    }

    // new_features[b][f][c][m] at 24576 + (g*128 + c)*128 + m
    float* fo = out + XYZ_OUT_ELEMS + (size_t)(g * 128) * 128 + m;
    fo[(size_t)(lane +  0) * 128] = facc0;
    fo[(size_t)(lane + 32) * 128] = facc1;
    fo[(size_t)(lane + 64) * 128] = facc2;
    fo[(size_t)(lane + 96) * 128] = facc3;
}

// ---------------------------------------------------------------------------
extern "C" void kernel_launch(void* const* d_in, const int* in_sizes, int n_in,
                              void* d_out, int out_size)
{
    const float* xyzs = (const float*)d_in[0];   // (4,32,4096,3) f32
    const float* Wd   = (const float*)d_in[1];   // (64,4) f32
    const float* Wm   = (const float*)d_in[2];   // (128,64) f32
    float* out = (float*)d_out;                  // 24576 xyz + 262144 feat

    fps_kernel<<<NGRP, 512>>>(xyzs, out);
    p4d_kernel<<<1024, 256>>>(xyzs, Wd, Wm, out);
}

// round 4
// speedup vs baseline: 1.0800x; 1.0800x over previous
#include <cuda_runtime.h>
#include <cstdint>

#define FULL_MASK 0xffffffffu

// B=4, T=32, N=4096, F=16, G=64, M=128, K=32, C0=64, C1=128
#define NPTS   4096
#define NGRP   64
#define NANCH  128
#define XYZ_OUT_ELEMS (64 * 128 * 3)   // 24576
#define R2CONST 0.0225f
#define WROW   34                      // u64 per padded row (32 used + 2 pad, 272B = 16B aligned)

typedef unsigned long long u64t;

static __device__ __forceinline__ u64t pack2(float lo, float hi) {
    u64t r;
    asm("mov.b64 %0, {%1, %2};" : "=l"(r) : "f"(lo), "f"(hi));
    return r;
}
static __device__ __forceinline__ void fma2(u64t &acc, u64t a, u64t b) {
    asm("fma.rn.f32x2 %0, %1, %2, %0;" : "+l"(acc) : "l"(a), "l"(b));
}
static __device__ __forceinline__ void add2(u64t &a, u64t b) {
    asm("add.rn.f32x2 %0, %0, %1;" : "+l"(a) : "l"(b));
}
static __device__ __forceinline__ float sum2(u64t v) {
    float a, b;
    asm("mov.b64 {%0, %1}, %2;" : "=f"(a), "=f"(b) : "l"(v));
    return a + b;
}

// ---------------------------------------------------------------------------
// Kernel 1: furthest point sampling. One block per group (64 blocks).
// Writes anchor coords directly into d_out[0 .. 24576) = new_xyzs.
// ---------------------------------------------------------------------------
__global__ __launch_bounds__(512) void fps_kernel(const float* __restrict__ xyzs,
                                                  float* __restrict__ out)
{
    __shared__ float sx[NPTS], sy[NPTS], sz[NPTS];
    __shared__ float wv[16];
    __shared__ int   wi[16];
    __shared__ float bc[3];

    const int g = blockIdx.x;
    const int b = g >> 4;
    const int f = g & 15;
    const int tc = 2 * f;
    const float* fr = xyzs + (size_t)((b * 32 + tc) * NPTS) * 3;

    const int tid  = threadIdx.x;
    const int lane = tid & 31;
    const int warp = tid >> 5;

    float px[8], py[8], pz[8], dist[8];
#pragma unroll
    for (int j = 0; j < 8; j++) {
        int p = tid * 8 + j;
        float x = fr[p * 3 + 0];
        float y = fr[p * 3 + 1];
        float z = fr[p * 3 + 2];
        px[j] = x; py[j] = y; pz[j] = z;
        sx[p] = x; sy[p] = y; sz[p] = z;
        dist[j] = 1e10f;
    }
    float* anc = out + (size_t)g * NANCH * 3;
    __syncthreads();
    if (tid == 0) {
        bc[0] = sx[0]; bc[1] = sy[0]; bc[2] = sz[0];
        anc[0] = sx[0]; anc[1] = sy[0]; anc[2] = sz[0];
    }
    __syncthreads();

    for (int it = 1; it < NANCH; it++) {
        const float cx = bc[0], cy = bc[1], cz = bc[2];
        float bd = -1.0f;
        int   bi = 0;
#pragma unroll
        for (int j = 0; j < 8; j++) {
            float dx = px[j] - cx, dy = py[j] - cy, dz = pz[j] - cz;
            float d = dx * dx + dy * dy + dz * dz;
            d = fminf(dist[j], d);
            dist[j] = d;
            if (d > bd) { bd = d; bi = tid * 8 + j; }   // strict > keeps earliest index
        }
#pragma unroll
        for (int off = 16; off > 0; off >>= 1) {
            float ov = __shfl_down_sync(FULL_MASK, bd, off);
            int   oi = __shfl_down_sync(FULL_MASK, bi, off);
            if (ov > bd) { bd = ov; bi = oi; }
        }
        if (lane == 0) { wv[warp] = bd; wi[warp] = bi; }
        __syncthreads();
        if (warp == 0) {
            float v  = (lane < 16) ? wv[lane] : -2.0f;
            int   i2 = (lane < 16) ? wi[lane] : 0;
#pragma unroll
            for (int off = 8; off > 0; off >>= 1) {
                float ov = __shfl_down_sync(FULL_MASK, v, off);
                int   oi = __shfl_down_sync(FULL_MASK, i2, off);
                if (ov > v) { v = ov; i2 = oi; }
            }
            if (lane == 0) {
                float nx = sx[i2], ny = sy[i2], nz = sz[i2];
                bc[0] = nx; bc[1] = ny; bc[2] = nz;
                anc[it * 3 + 0] = nx;
                anc[it * 3 + 1] = ny;
                anc[it * 3 + 2] = nz;
            }
        }
        __syncthreads();
    }
}

// ---------------------------------------------------------------------------
// Kernel 2: ball query + MLP(4->64) + MLP(64->128) + max over neighbors.
// One warp per anchor. 8 warps/block, 1024 blocks. Shuffle-free GEMM phase:
// h1 staged in smem per warp, lanes own 4 output channels each, Wm row in
// registers, h1 streamed via broadcast LDS.128, running max in a register.
// ---------------------------------------------------------------------------
__global__ __launch_bounds__(256, 2) void p4d_kernel(const float* __restrict__ xyzs,
                                                     const float* __restrict__ Wd,
                                                     const float* __restrict__ Wm,
                                                     float* __restrict__ out)
{
    extern __shared__ __align__(16) u64t smem_dyn[];
    u64t*  Wm2  = smem_dyn;                          // 128 rows x WROW u64
    u64t*  H1   = smem_dyn + 128 * WROW;             // 8 warps x 32 rows x WROW u64
    float* Wd_s = (float*)(H1 + 8 * 32 * WROW);      // 256 floats
    int*   sel  = (int*)(Wd_s + 256);                // 8 x 32 ints

    const int tid = threadIdx.x;

    // Load Wm into padded smem rows (u64-packed float pairs)
    const u64t* gWm = (const u64t*)Wm;
    for (int i = tid; i < 128 * 32; i += 256) {
        int c = i >> 5, i2 = i & 31;
        Wm2[c * WROW + i2] = gWm[i];
    }
    Wd_s[tid] = Wd[tid];
    __syncthreads();

    const int lane = tid & 31;
    const int w    = tid >> 5;
    const int a    = blockIdx.x * 8 + w;      // global anchor id 0..8191
    const int g    = a >> 7;
    const int m    = a & 127;
    const int b    = g >> 4;
    const int f    = g & 15;
    const int tc   = 2 * f;

    const float* anc = out + (size_t)(g * NANCH + m) * 3;
    const float ax = anc[0], ay = anc[1], az = anc[2];

    const float4* Wd4  = (const float4*)Wd_s;
    int*          selw = sel + w * 32;
    u64t*         hrow = H1 + (size_t)(w * 32 + lane) * WROW;
    const u64t*   hb   = H1 + (size_t)(w * 32) * WROW;

    float facc0 = 0.f, facc1 = 0.f, facc2 = 0.f, facc3 = 0.f;

    for (int dti = 0; dti < 3; dti++) {
        const int t = (dti == 0) ? ((f == 0) ? 0 : (tc - 1))
                                 : ((dti == 1) ? tc : (tc + 1));
        const float* fr  = xyzs + (size_t)((b * 32 + t) * NPTS) * 3;
        const float  dtf = (float)(dti - 1);

        // ---- ball query: first 32 in-radius indices (ascending), pad with first
        __syncwarp();
        int cnt = 0;
        for (int base = 0; base < NPTS && cnt < 32; base += 32) {
            const int idx = base + lane;
            const float nx = fr[idx * 3 + 0];
            const float ny = fr[idx * 3 + 1];
            const float nz = fr[idx * 3 + 2];
            const float dx = nx - ax, dy = ny - ay, dz = nz - az;
            const float d2 = dx * dx + dy * dy + dz * dz;
            const bool  pr = d2 < R2CONST;
            const unsigned mask = __ballot_sync(FULL_MASK, pr);
            const int rank = cnt + __popc(mask & ((1u << lane) - 1u));
            if (pr && rank < 32) selw[rank] = idx;
            cnt += __popc(mask);
        }
        __syncwarp();
        const int pad = (cnt > 0) ? selw[0] : 0;
        const int myN = (lane < cnt) ? selw[lane] : pad;

        const float nx = fr[myN * 3 + 0];
        const float ny = fr[myN * 3 + 1];
        const float nz = fr[myN * 3 + 2];
        const float dx = nx - ax, dy = ny - ay, dz = nz - az;

        // ---- h1 = relu(Wd @ [dx,dy,dz,dt]) : 64 values -> smem row (f32x2)
        {
            ulonglong2* hv = (ulonglong2*)hrow;
#pragma unroll
            for (int k = 0; k < 16; k++) {
                const float4 w0 = Wd4[4 * k + 0];
                const float4 w1 = Wd4[4 * k + 1];
                const float4 w2 = Wd4[4 * k + 2];
                const float4 w3 = Wd4[4 * k + 3];
                float a0 = fmaxf(w0.x * dx + w0.y * dy + w0.z * dz + w0.w * dtf, 0.f);
                float a1 = fmaxf(w1.x * dx + w1.y * dy + w1.z * dz + w1.w * dtf, 0.f);
                float a2 = fmaxf(w2.x * dx + w2.y * dy + w2.z * dz + w2.w * dtf, 0.f);
                float a3 = fmaxf(w3.x * dx + w3.y * dy + w3.z * dz + w3.w * dtf, 0.f);
                ulonglong2 v; v.x = pack2(a0, a1); v.y = pack2(a2, a3);
                hv[k] = v;
            }
        }
        __syncwarp();

        // ---- h2 = Wm @ h1, running max over 32 neighbors. Lane owns 4 channels.
#pragma unroll
        for (int cc = 0; cc < 4; cc++) {
            const ulonglong2* wr = (const ulonglong2*)(Wm2 + (size_t)(cc * 32 + lane) * WROW);
            u64t wreg[32];
#pragma unroll
            for (int k = 0; k < 16; k++) {
                ulonglong2 tld = wr[k];
                wreg[2 * k]     = tld.x;
                wreg[2 * k + 1] = tld.y;
            }
            float mx = -1e30f;
#pragma unroll 2
            for (int n = 0; n < 32; n++) {
                const ulonglong2* hr = (const ulonglong2*)(hb + (size_t)n * WROW);
                u64t a0 = 0ull, a1 = 0ull, a2 = 0ull, a3 = 0ull;
#pragma unroll
                for (int k = 0; k < 8; k++) {
                    ulonglong2 p = hr[2 * k];
                    ulonglong2 q = hr[2 * k + 1];
                    fma2(a0, wreg[4 * k + 0], p.x);
                    fma2(a1, wreg[4 * k + 1], p.y);
                    fma2(a2, wreg[4 * k + 2], q.x);
                    fma2(a3, wreg[4 * k + 3], q.y);
                }
                add2(a0, a1);
                add2(a2, a3);
                add2(a0, a2);
                mx = fmaxf(mx, sum2(a0));
            }
            const float r = fmaxf(mx, 0.f);
            if      (cc == 0) facc0 += r;
            else if (cc == 1) facc1 += r;
            else if (cc == 2) facc2 += r;
            else              facc3 += r;
        }
        __syncwarp();   // protect H1 rows before next dt overwrites them
    }

    // new_features[b][f][c][m] at 24576 + (g*128 + c)*128 + m
    float* fo = out + XYZ_OUT_ELEMS + (size_t)(g * 128) * 128 + m;
    fo[(size_t)(lane +  0) * 128] = facc0;
    fo[(size_t)(lane + 32) * 128] = facc1;
    fo[(size_t)(lane + 64) * 128] = facc2;
    fo[(size_t)(lane + 96) * 128] = facc3;
}

// ---------------------------------------------------------------------------
extern "C" void kernel_launch(void* const* d_in, const int* in_sizes, int n_in,
                              void* d_out, int out_size)
{
    const float* xyzs = (const float*)d_in[0];   // (4,32,4096,3) f32
    const float* Wd   = (const float*)d_in[1];   // (64,4) f32
    const float* Wm   = (const float*)d_in[2];   // (128,64) f32
    float* out = (float*)d_out;                  // 24576 xyz + 262144 feat

    const int smem_bytes = (128 * WROW + 8 * 32 * WROW) * 8 + 1024 + 1024; // 106496
    static bool attr_set = false;
    (void)attr_set;
    cudaFuncSetAttribute(p4d_kernel, cudaFuncAttributeMaxDynamicSharedMemorySize,
                         smem_bytes);

    fps_kernel<<<NGRP, 512>>>(xyzs, out);
    p4d_kernel<<<1024, 256, smem_bytes>>>(xyzs, Wd, Wm, out);
}

// round 11
// speedup vs baseline: 1.4908x; 1.3805x over previous
#include <cuda_runtime.h>
#include <cstdint>

#define FULL_MASK 0xffffffffu

// B=4, T=32, N=4096, F=16, G=64, M=128, K=32, C0=64, C1=128
#define NPTS   4096
#define NGRP   64
#define NANCH  128
#define XYZ_OUT_ELEMS (64 * 128 * 3)   // 24576
#define R2CONST 0.0225f

typedef unsigned long long u64t;

static __device__ __forceinline__ u64t pack2(float lo, float hi) {
    u64t r;
    asm("mov.b64 %0, {%1, %2};" : "=l"(r) : "f"(lo), "f"(hi));
    return r;
}
static __device__ __forceinline__ void fma2(u64t &acc, u64t a, u64t b) {
    asm("fma.rn.f32x2 %0, %1, %2, %0;" : "+l"(acc) : "l"(a), "l"(b));
}
static __device__ __forceinline__ void add2(u64t &a, u64t b) {
    asm("add.rn.f32x2 %0, %0, %1;" : "+l"(a) : "l"(b));
}
static __device__ __forceinline__ float sum2(u64t v) {
    float a, b;
    asm("mov.b64 {%0, %1}, %2;" : "=f"(a), "=f"(b) : "l"(v));
    return a + b;
}
// Warp max of a NON-NEGATIVE float: non-negative IEEE bits are monotone as u32,
// so integer redux (sm_80+ baseline, valid on sm_103a) gives an exact fp32 max.
static __device__ __forceinline__ float warp_max_nn(float s) {
    unsigned r;
    asm volatile("redux.sync.max.u32 %0, %1, 0xffffffff;"
                 : "=r"(r) : "r"(__float_as_uint(s)));
    return __uint_as_float(r);
}

// ---------------------------------------------------------------------------
// Kernel 1: furthest point sampling. One block per group (64 blocks).
// Writes anchor coords directly into d_out[0 .. 24576) = new_xyzs.
// ---------------------------------------------------------------------------
__global__ __launch_bounds__(512) void fps_kernel(const float* __restrict__ xyzs,
                                                  float* __restrict__ out)
{
    __shared__ float sx[NPTS], sy[NPTS], sz[NPTS];
    __shared__ float wv[16];
    __shared__ int   wi[16];
    __shared__ float bc[3];

    const int g = blockIdx.x;
    const int b = g >> 4;
    const int f = g & 15;
    const int tc = 2 * f;
    const float* fr = xyzs + (size_t)((b * 32 + tc) * NPTS) * 3;

    const int tid  = threadIdx.x;
    const int lane = tid & 31;
    const int warp = tid >> 5;

    float px[8], py[8], pz[8], dist[8];
#pragma unroll
    for (int j = 0; j < 8; j++) {
        int p = tid * 8 + j;
        float x = fr[p * 3 + 0];
        float y = fr[p * 3 + 1];
        float z = fr[p * 3 + 2];
        px[j] = x; py[j] = y; pz[j] = z;
        sx[p] = x; sy[p] = y; sz[p] = z;
        dist[j] = 1e10f;
    }
    float* anc = out + (size_t)g * NANCH * 3;
    __syncthreads();
    if (tid == 0) {
        bc[0] = sx[0]; bc[1] = sy[0]; bc[2] = sz[0];
        anc[0] = sx[0]; anc[1] = sy[0]; anc[2] = sz[0];
    }
    __syncthreads();

    for (int it = 1; it < NANCH; it++) {
        const float cx = bc[0], cy = bc[1], cz = bc[2];
        float bd = -1.0f;
        int   bi = 0;
#pragma unroll
        for (int j = 0; j < 8; j++) {
            float dx = px[j] - cx, dy = py[j] - cy, dz = pz[j] - cz;
            float d = dx * dx + dy * dy + dz * dz;
            d = fminf(dist[j], d);
            dist[j] = d;
            if (d > bd) { bd = d; bi = tid * 8 + j; }   // strict > keeps earliest index
        }
#pragma unroll
        for (int off = 16; off > 0; off >>= 1) {
            float ov = __shfl_down_sync(FULL_MASK, bd, off);
            int   oi = __shfl_down_sync(FULL_MASK, bi, off);
            if (ov > bd) { bd = ov; bi = oi; }
        }
        if (lane == 0) { wv[warp] = bd; wi[warp] = bi; }
        __syncthreads();
        if (warp == 0) {
            float v  = (lane < 16) ? wv[lane] : -2.0f;
            int   i2 = (lane < 16) ? wi[lane] : 0;
#pragma unroll
            for (int off = 8; off > 0; off >>= 1) {
                float ov = __shfl_down_sync(FULL_MASK, v, off);
                int   oi = __shfl_down_sync(FULL_MASK, i2, off);
                if (ov > v) { v = ov; i2 = oi; }
            }
            if (lane == 0) {
                float nx = sx[i2], ny = sy[i2], nz = sz[i2];
                bc[0] = nx; bc[1] = ny; bc[2] = nz;
                anc[it * 3 + 0] = nx;
                anc[it * 3 + 1] = ny;
                anc[it * 3 + 2] = nz;
            }
        }
        __syncthreads();
    }
}

// ---------------------------------------------------------------------------
// Kernel 2: ball query + MLP(4->64) + MLP(64->128) + max over neighbors.
// One warp per anchor, lane = neighbor. h1 (64 vals) lives in registers as
// 32 f32x2; Wm rows streamed via broadcast LDS.128; per-channel warp max via
// redux.sync.max.u32 on pre-relu-clamped (non-negative) values.
// ---------------------------------------------------------------------------
__global__ __launch_bounds__(256, 2) void p4d_kernel(const float* __restrict__ xyzs,
                                                     const float* __restrict__ Wd,
                                                     const float* __restrict__ Wm,
                                                     float* __restrict__ out)
{
    __shared__ __align__(16) float Wm_s[128 * 64];
    __shared__ __align__(16) float Wd_s[256];
    __shared__ int sel[8][32];

    const int tid = threadIdx.x;
    {
        const float4* gWm = (const float4*)Wm;
        float4*       sWm = (float4*)Wm_s;
        for (int i = tid; i < 128 * 16; i += 256) sWm[i] = gWm[i];
        Wd_s[tid] = Wd[tid];
    }
    __syncthreads();

    const int lane = tid & 31;
    const int w    = tid >> 5;
    const int a    = blockIdx.x * 8 + w;      // global anchor id 0..8191
    const int g    = a >> 7;
    const int m    = a & 127;
    const int b    = g >> 4;
    const int f    = g & 15;
    const int tc   = 2 * f;

    const float* anc = out + (size_t)(g * NANCH + m) * 3;
    const float ax = anc[0], ay = anc[1], az = anc[2];

    const float4* Wd4  = (const float4*)Wd_s;
    int*          selw = sel[w];

    float facc0 = 0.f, facc1 = 0.f, facc2 = 0.f, facc3 = 0.f;

    for (int dti = 0; dti < 3; dti++) {
        const int t = (dti == 0) ? ((f == 0) ? 0 : (tc - 1))
                                 : ((dti == 1) ? tc : (tc + 1));
        const float* fr  = xyzs + (size_t)((b * 32 + t) * NPTS) * 3;
        const float  dtf = (float)(dti - 1);

        // ---- ball query: first 32 in-radius indices (ascending), pad w/ first.
        //      Batched: 128 points (4 ballots) per trip, loads issued up front.
        __syncwarp();
        int cnt = 0;
        for (int base = 0; base < NPTS && cnt < 32; base += 128) {
            unsigned masks[4];
#pragma unroll
            for (int j = 0; j < 4; j++) {
                const int idx = base + j * 32 + lane;
                const float nx = fr[idx * 3 + 0];
                const float ny = fr[idx * 3 + 1];
                const float nz = fr[idx * 3 + 2];
                const float dx = nx - ax, dy = ny - ay, dz = nz - az;
                const float d2 = dx * dx + dy * dy + dz * dz;
                masks[j] = __ballot_sync(FULL_MASK, d2 < R2CONST);
            }
#pragma unroll
            for (int j = 0; j < 4; j++) {
                const unsigned mk = masks[j];
                const bool pr = (mk >> lane) & 1u;
                const int rank = cnt + __popc(mk & ((1u << lane) - 1u));
                if (pr && rank < 32) selw[rank] = base + j * 32 + lane;
                cnt += __popc(mk);
            }
        }
        __syncwarp();
        const int pad = (cnt > 0) ? selw[0] : 0;
        const int myN = (lane < cnt) ? selw[lane] : pad;

        const float nx = fr[myN * 3 + 0];
        const float ny = fr[myN * 3 + 1];
        const float nz = fr[myN * 3 + 2];
        const float dx = nx - ax, dy = ny - ay, dz = nz - az;

        // ---- h1 = relu(Wd @ [dx,dy,dz,dt]) : 64 values in regs as 32 f32x2
        u64t Hp[32];
#pragma unroll
        for (int i2 = 0; i2 < 32; i2++) {
            const float4 w0 = Wd4[2 * i2];
            const float4 w1 = Wd4[2 * i2 + 1];
            float a0 = fmaxf(w0.x * dx + w0.y * dy + w0.z * dz + w0.w * dtf, 0.f);
            float a1 = fmaxf(w1.x * dx + w1.y * dy + w1.z * dz + w1.w * dtf, 0.f);
            Hp[i2] = pack2(a0, a1);
        }

        // ---- h2 = Wm @ h1 per lane(=neighbor); relu then warp max per channel.
        //      Lane `ol` owns channel cc*32+ol.
#pragma unroll
        for (int cc = 0; cc < 4; cc++) {
            float fa = 0.f;
#pragma unroll 2
            for (int ol = 0; ol < 32; ol++) {
                const ulonglong2* wr =
                    (const ulonglong2*)(Wm_s + ((cc * 32 + ol) << 6));
                u64t a0 = 0ull, a1 = 0ull, a2 = 0ull, a3 = 0ull;
#pragma unroll
                for (int k = 0; k < 8; k++) {
                    ulonglong2 p = wr[2 * k];
                    ulonglong2 q = wr[2 * k + 1];
                    fma2(a0, p.x, Hp[4 * k + 0]);
                    fma2(a1, p.y, Hp[4 * k + 1]);
                    fma2(a2, q.x, Hp[4 * k + 2]);
                    fma2(a3, q.y, Hp[4 * k + 3]);
                }
                add2(a0, a1);
                add2(a2, a3);
                add2(a0, a2);
                const float r = warp_max_nn(fmaxf(sum2(a0), 0.f));
                if (ol == lane) fa += r;
            }
            if      (cc == 0) facc0 += fa;
            else if (cc == 1) facc1 += fa;
            else if (cc == 2) facc2 += fa;
            else              facc3 += fa;
        }
    }

    // new_features[b][f][c][m] at 24576 + (g*128 + c)*128 + m
    float* fo = out + XYZ_OUT_ELEMS + (size_t)(g * 128) * 128 + m;
    fo[(size_t)(lane +  0) * 128] = facc0;
    fo[(size_t)(lane + 32) * 128] = facc1;
    fo[(size_t)(lane + 64) * 128] = facc2;
    fo[(size_t)(lane + 96) * 128] = facc3;
}

// ---------------------------------------------------------------------------
extern "C" void kernel_launch(void* const* d_in, const int* in_sizes, int n_in,
                              void* d_out, int out_size)
{
    const float* xyzs = (const float*)d_in[0];   // (4,32,4096,3) f32
    const float* Wd   = (const float*)d_in[1];   // (64,4) f32
    const float* Wm   = (const float*)d_in[2];   // (128,64) f32
    float* out = (float*)d_out;                  // 24576 xyz + 262144 feat

    fps_kernel<<<NGRP, 512>>>(xyzs, out);
    p4d_kernel<<<1024, 256>>>(xyzs, Wd, Wm, out);
}